// round 1
// baseline (speedup 1.0000x reference)
#include <cuda_runtime.h>
#include <math.h>

// Problem constants
#define BATCH 2
#define TLEN 2048
#define MLEN 77
#define CDIM 512
#define HEADS 8
#define DHEAD 64
#define BT (BATCH * TLEN)      // 4096
#define NBIG (BT * CDIM)       // 2097152
#define NSMALL (BATCH * MLEN * CDIM) // 78848

// Scratch layout: Q,K,V,Y,YC,G1,G2,FUSED (each NBIG) then KC, VC
__device__ float g_scratch[8ULL * NBIG + 2ULL * NSMALL];

// ---------------------------------------------------------------------------
// GEMM: out[M,512] = A[M,512] @ W[512,512] + bias ; BM=128, BN=64, BK=16
// 256 threads, thread tile 8x4
// ---------------------------------------------------------------------------
__global__ __launch_bounds__(256) void gemm_bias_kernel(
    const float* __restrict__ A, const float* __restrict__ W,
    const float* __restrict__ bias, float* __restrict__ out, int Mrows)
{
    __shared__ float sA[16 * 128];   // [kk][m]
    __shared__ float sW[16 * 64];    // [kk][n]

    const int tid = threadIdx.x;
    const int tx = tid & 15;         // 0..15 -> n groups of 4
    const int ty = tid >> 4;         // 0..15 -> m groups of 8
    const int m0 = blockIdx.y * 128;
    const int n0 = blockIdx.x * 64;

    float acc[8][4];
#pragma unroll
    for (int r = 0; r < 8; ++r)
#pragma unroll
        for (int c = 0; c < 4; ++c) acc[r][c] = 0.f;

    // A-load mapping: m = tid/2, kb = (tid&1)*8 -> two float4
    const int am = tid >> 1;
    const int akb = (tid & 1) * 8;
    // W-load mapping: kk = tid/16, n = (tid&15)*4 -> one float4
    const int wk = tid >> 4;
    const int wn = (tid & 15) * 4;

    for (int k0 = 0; k0 < 512; k0 += 16) {
        __syncthreads();
        // load A tile (guarded)
        {
            const int row = m0 + am;
            float4 a0, a1;
            if (row < Mrows) {
                const float* ap = A + (size_t)row * 512 + k0 + akb;
                a0 = *reinterpret_cast<const float4*>(ap);
                a1 = *reinterpret_cast<const float4*>(ap + 4);
            } else {
                a0 = make_float4(0.f, 0.f, 0.f, 0.f);
                a1 = a0;
            }
            sA[(akb + 0) * 128 + am] = a0.x;
            sA[(akb + 1) * 128 + am] = a0.y;
            sA[(akb + 2) * 128 + am] = a0.z;
            sA[(akb + 3) * 128 + am] = a0.w;
            sA[(akb + 4) * 128 + am] = a1.x;
            sA[(akb + 5) * 128 + am] = a1.y;
            sA[(akb + 6) * 128 + am] = a1.z;
            sA[(akb + 7) * 128 + am] = a1.w;
        }
        // load W tile
        {
            const float4 w = *reinterpret_cast<const float4*>(
                W + (size_t)(k0 + wk) * 512 + n0 + wn);
            *reinterpret_cast<float4*>(&sW[wk * 64 + wn]) = w;
        }
        __syncthreads();

#pragma unroll
        for (int kk = 0; kk < 16; ++kk) {
            const float4 a0 = *reinterpret_cast<const float4*>(&sA[kk * 128 + ty * 8]);
            const float4 a1 = *reinterpret_cast<const float4*>(&sA[kk * 128 + ty * 8 + 4]);
            const float4 b  = *reinterpret_cast<const float4*>(&sW[kk * 64 + tx * 4]);
            const float a[8] = {a0.x, a0.y, a0.z, a0.w, a1.x, a1.y, a1.z, a1.w};
            const float bb[4] = {b.x, b.y, b.z, b.w};
#pragma unroll
            for (int r = 0; r < 8; ++r)
#pragma unroll
                for (int c = 0; c < 4; ++c)
                    acc[r][c] = fmaf(a[r], bb[c], acc[r][c]);
        }
    }

    const float4 bv = *reinterpret_cast<const float4*>(bias + n0 + tx * 4);
#pragma unroll
    for (int r = 0; r < 8; ++r) {
        const int row = m0 + ty * 8 + r;
        if (row < Mrows) {
            float4 o;
            o.x = acc[r][0] + bv.x;
            o.y = acc[r][1] + bv.y;
            o.z = acc[r][2] + bv.z;
            o.w = acc[r][3] + bv.w;
            *reinterpret_cast<float4*>(out + (size_t)row * 512 + n0 + tx * 4) = o;
        }
    }
}

// ---------------------------------------------------------------------------
// Flash self-attention (causal), fp32. 64x64 blocks, 256 threads (16x16),
// thread tile 4x4. Q/K/V stored as [B,T,C] with head at col offset h*64.
// grid: (T/64, B*H)
// ---------------------------------------------------------------------------
__global__ __launch_bounds__(256) void self_attn_kernel(
    const float* __restrict__ Q, const float* __restrict__ K,
    const float* __restrict__ V, float* __restrict__ Y)
{
    const int qb = blockIdx.x;
    const int bh = blockIdx.y;
    const int b = bh >> 3;
    const int h = bh & 7;

    extern __shared__ float sm[];
    float* sQ = sm;                // 64*65
    float* sK = sm + 64 * 65;
    float* sV = sm + 2 * 64 * 65;
    float* sP = sm + 3 * 64 * 65;

    const int tid = threadIdx.x;
    const int tx = tid & 15;
    const int ty = tid >> 4;

    const size_t base = ((size_t)b * TLEN) * CDIM + h * DHEAD;

    // load Q block
    for (int i = tid; i < 64 * 64; i += 256) {
        const int r = i >> 6, c = i & 63;
        sQ[r * 65 + c] = Q[base + (size_t)(qb * 64 + r) * CDIM + c];
    }

    float acc[4][4];
    float mi[4], li[4];
#pragma unroll
    for (int r = 0; r < 4; ++r) {
        mi[r] = -1e30f;
        li[r] = 0.f;
#pragma unroll
        for (int c = 0; c < 4; ++c) acc[r][c] = 0.f;
    }

    for (int jb = 0; jb <= qb; ++jb) {
        __syncthreads();  // protect sK/sV/sP from prior iteration readers
        for (int i = tid; i < 64 * 64; i += 256) {
            const int r = i >> 6, c = i & 63;
            const size_t g = base + (size_t)(jb * 64 + r) * CDIM + c;
            sK[r * 65 + c] = K[g];
            sV[r * 65 + c] = V[g];
        }
        __syncthreads();

        // S = Q @ K^T
        float s[4][4];
#pragma unroll
        for (int r = 0; r < 4; ++r)
#pragma unroll
            for (int c = 0; c < 4; ++c) s[r][c] = 0.f;

#pragma unroll 8
        for (int d = 0; d < 64; ++d) {
            float qv[4], kv[4];
#pragma unroll
            for (int r = 0; r < 4; ++r) qv[r] = sQ[(ty * 4 + r) * 65 + d];
#pragma unroll
            for (int c = 0; c < 4; ++c) kv[c] = sK[(tx * 4 + c) * 65 + d];
#pragma unroll
            for (int r = 0; r < 4; ++r)
#pragma unroll
                for (int c = 0; c < 4; ++c)
                    s[r][c] = fmaf(qv[r], kv[c], s[r][c]);
        }

        // scale + causal mask
        const bool diag = (jb == qb);
#pragma unroll
        for (int r = 0; r < 4; ++r) {
            const int gi = qb * 64 + ty * 4 + r;
#pragma unroll
            for (int c = 0; c < 4; ++c) {
                const int gj = jb * 64 + tx * 4 + c;
                float sv = s[r][c] * 0.125f;
                if (diag && gj > gi) sv = -1e30f;
                s[r][c] = sv;
            }
        }

        // online softmax (row reduce over 16 lanes)
#pragma unroll
        for (int r = 0; r < 4; ++r) {
            float rm = fmaxf(fmaxf(s[r][0], s[r][1]), fmaxf(s[r][2], s[r][3]));
#pragma unroll
            for (int off = 8; off >= 1; off >>= 1)
                rm = fmaxf(rm, __shfl_xor_sync(0xffffffffu, rm, off));
            const float mnew = fmaxf(mi[r], rm);
            const float corr = __expf(mi[r] - mnew);
            float p[4], rs = 0.f;
#pragma unroll
            for (int c = 0; c < 4; ++c) {
                p[c] = __expf(s[r][c] - mnew);
                rs += p[c];
            }
#pragma unroll
            for (int off = 8; off >= 1; off >>= 1)
                rs += __shfl_xor_sync(0xffffffffu, rs, off);
            li[r] = li[r] * corr + rs;
            mi[r] = mnew;
#pragma unroll
            for (int c = 0; c < 4; ++c) {
                acc[r][c] *= corr;
                sP[(ty * 4 + r) * 65 + tx * 4 + c] = p[c];
            }
        }
        __syncthreads();

        // O += P @ V
#pragma unroll 8
        for (int j = 0; j < 64; ++j) {
            float vv[4];
#pragma unroll
            for (int c = 0; c < 4; ++c) vv[c] = sV[j * 65 + tx * 4 + c];
#pragma unroll
            for (int r = 0; r < 4; ++r) {
                const float pv = sP[(ty * 4 + r) * 65 + j];
#pragma unroll
                for (int c = 0; c < 4; ++c)
                    acc[r][c] = fmaf(pv, vv[c], acc[r][c]);
            }
        }
    }

#pragma unroll
    for (int r = 0; r < 4; ++r) {
        const float inv = 1.f / li[r];
#pragma unroll
        for (int c = 0; c < 4; ++c)
            Y[base + (size_t)(qb * 64 + ty * 4 + r) * CDIM + tx * 4 + c] =
                acc[r][c] * inv;
    }
}

// ---------------------------------------------------------------------------
// Cross-attention: 77 keys per head, padding mask. One thread per query row.
// grid: (T/128, B*H), 128 threads.
// ---------------------------------------------------------------------------
__global__ __launch_bounds__(128) void cross_attn_kernel(
    const float* __restrict__ Q, const float* __restrict__ Kc,
    const float* __restrict__ Vc, const int* __restrict__ pad,
    float* __restrict__ Yc)
{
    const int bh = blockIdx.y;
    const int b = bh >> 3;
    const int h = bh & 7;
    const int row0 = blockIdx.x * 128;
    const int tid = threadIdx.x;

    __shared__ float sQ[128 * 65];

    const size_t qbase = ((size_t)b * TLEN) * CDIM + h * DHEAD;
    for (int i = tid; i < 128 * 64; i += 128) {
        const int r = i >> 6, c = i & 63;
        sQ[r * 65 + c] = Q[qbase + (size_t)(row0 + r) * CDIM + c];
    }
    __syncthreads();

    const float* kb = Kc + ((size_t)b * MLEN) * CDIM + h * DHEAD;
    const float* vb = Vc + ((size_t)b * MLEN) * CDIM + h * DHEAD;
    const int* pb = pad + b * MLEN;
    const float* qrow = &sQ[tid * 65];

    // pass 1: max
    float m = -1e30f;
    for (int j = 0; j < MLEN; ++j) {
        if (pb[j] == 0) continue;
        float dot = 0.f;
        const float* kr = kb + (size_t)j * CDIM;
#pragma unroll 16
        for (int d = 0; d < 64; ++d) dot = fmaf(qrow[d], kr[d], dot);
        m = fmaxf(m, dot * 0.125f);
    }

    // pass 2: accumulate
    float l = 0.f;
    float o[64];
#pragma unroll
    for (int d = 0; d < 64; ++d) o[d] = 0.f;

    for (int j = 0; j < MLEN; ++j) {
        if (pb[j] == 0) continue;
        float dot = 0.f;
        const float* kr = kb + (size_t)j * CDIM;
#pragma unroll 16
        for (int d = 0; d < 64; ++d) dot = fmaf(qrow[d], kr[d], dot);
        const float p = __expf(dot * 0.125f - m);
        l += p;
        const float* vr = vb + (size_t)j * CDIM;
#pragma unroll 16
        for (int d = 0; d < 64; ++d) o[d] = fmaf(p, vr[d], o[d]);
    }

    const float inv = (l > 0.f) ? (1.f / l) : 0.f;
    float* yout = Yc + qbase + (size_t)(row0 + tid) * CDIM;
#pragma unroll 16
    for (int d = 0; d < 64; ++d) yout[d] = o[d] * inv;
}

// ---------------------------------------------------------------------------
// fused = sigmoid(g1) * yc + sigmoid(g2) * y
// ---------------------------------------------------------------------------
__device__ __forceinline__ float sigf(float x) {
    return 1.f / (1.f + __expf(-x));
}

__global__ __launch_bounds__(256) void gate_fuse_kernel(
    const float* __restrict__ g1, const float* __restrict__ g2,
    const float* __restrict__ y, const float* __restrict__ yc,
    float* __restrict__ out)
{
    const int i = blockIdx.x * blockDim.x + threadIdx.x;  // float4 index
    const float4 a = reinterpret_cast<const float4*>(g1)[i];
    const float4 bg = reinterpret_cast<const float4*>(g2)[i];
    const float4 yv = reinterpret_cast<const float4*>(y)[i];
    const float4 yw = reinterpret_cast<const float4*>(yc)[i];
    float4 o;
    o.x = sigf(a.x) * yw.x + sigf(bg.x) * yv.x;
    o.y = sigf(a.y) * yw.y + sigf(bg.y) * yv.y;
    o.z = sigf(a.z) * yw.z + sigf(bg.z) * yv.z;
    o.w = sigf(a.w) * yw.w + sigf(bg.w) * yv.w;
    reinterpret_cast<float4*>(out)[i] = o;
}

// ---------------------------------------------------------------------------
// Launch
// ---------------------------------------------------------------------------
extern "C" void kernel_launch(void* const* d_in, const int* in_sizes, int n_in,
                              void* d_out, int out_size)
{
    const float* x  = (const float*)d_in[0];
    const float* c  = (const float*)d_in[1];
    // d_in[2] attn_mask: fixed causal tril -> handled analytically
    const int* pad  = (const int*)d_in[3];
    const float* Wq = (const float*)d_in[4];
    const float* bq = (const float*)d_in[5];
    const float* Wk = (const float*)d_in[6];
    const float* bk = (const float*)d_in[7];
    const float* Wv = (const float*)d_in[8];
    const float* bv = (const float*)d_in[9];
    const float* Wkc = (const float*)d_in[10];
    const float* bkc = (const float*)d_in[11];
    const float* Wvc = (const float*)d_in[12];
    const float* bvc = (const float*)d_in[13];
    const float* Wg1 = (const float*)d_in[14];
    const float* bg1 = (const float*)d_in[15];
    const float* Wg2 = (const float*)d_in[16];
    const float* bg2 = (const float*)d_in[17];
    const float* Wp = (const float*)d_in[18];
    const float* bp = (const float*)d_in[19];
    float* out = (float*)d_out;

    float* S = nullptr;
    cudaGetSymbolAddress((void**)&S, g_scratch);
    float* Qb = S + 0ULL * NBIG;
    float* Kb = S + 1ULL * NBIG;
    float* Vb = S + 2ULL * NBIG;
    float* Yb = S + 3ULL * NBIG;
    float* YCb = S + 4ULL * NBIG;
    float* G1b = S + 5ULL * NBIG;
    float* G2b = S + 6ULL * NBIG;
    float* Fb = S + 7ULL * NBIG;
    float* KCb = S + 8ULL * NBIG;
    float* VCb = S + 8ULL * NBIG + NSMALL;

    const int SMEM_SA = 4 * 64 * 65 * (int)sizeof(float);  // 66560
    cudaFuncSetAttribute(self_attn_kernel,
                         cudaFuncAttributeMaxDynamicSharedMemorySize, SMEM_SA);

    const dim3 gemm_block(256);
    const dim3 gemm_grid_big(512 / 64, (BT + 127) / 128);     // (8, 32)
    const dim3 gemm_grid_small(512 / 64, (BATCH * MLEN + 127) / 128);  // (8, 2)

    // Projections
    gemm_bias_kernel<<<gemm_grid_big, gemm_block>>>(x, Wq, bq, Qb, BT);
    gemm_bias_kernel<<<gemm_grid_big, gemm_block>>>(x, Wk, bk, Kb, BT);
    gemm_bias_kernel<<<gemm_grid_big, gemm_block>>>(x, Wv, bv, Vb, BT);
    gemm_bias_kernel<<<gemm_grid_small, gemm_block>>>(c, Wkc, bkc, KCb, BATCH * MLEN);
    gemm_bias_kernel<<<gemm_grid_small, gemm_block>>>(c, Wvc, bvc, VCb, BATCH * MLEN);

    // Attention branches
    self_attn_kernel<<<dim3(TLEN / 64, BATCH * HEADS), 256, SMEM_SA>>>(Qb, Kb, Vb, Yb);
    cross_attn_kernel<<<dim3(TLEN / 128, BATCH * HEADS), 128>>>(Qb, KCb, VCb, pad, YCb);

    // Gates
    gemm_bias_kernel<<<gemm_grid_big, gemm_block>>>(Yb, Wg1, bg1, G1b, BT);
    gemm_bias_kernel<<<gemm_grid_big, gemm_block>>>(YCb, Wg2, bg2, G2b, BT);

    // fused = sig(G1)*YC + sig(G2)*Y
    gate_fuse_kernel<<<NBIG / 4 / 256, 256>>>(G1b, G2b, Yb, YCb, Fb);

    // output projection
    gemm_bias_kernel<<<gemm_grid_big, gemm_block>>>(Fb, Wp, bp, out, BT);
}

// round 2
// speedup vs baseline: 1.8362x; 1.8362x over previous
#include <cuda_runtime.h>
#include <math.h>
#include <stdint.h>

// Problem constants
#define BATCH 2
#define TLEN 2048
#define MLEN 77
#define CDIM 512
#define HEADS 8
#define DHEAD 64
#define BT (BATCH * TLEN)      // 4096
#define NBIG (BT * CDIM)       // 2097152
#define NSMALL (BATCH * MLEN * CDIM) // 78848
#define MSMALL (BATCH * MLEN)  // 154

// Scratch layout: Q,K,V,Y,YC,G1,G2,FUSED (each NBIG) then KC, VC
__device__ float g_scratch[8ULL * NBIG + 2ULL * NSMALL];

// ---------------------------------------------------------------------------
// tf32 helpers
// ---------------------------------------------------------------------------
__device__ __forceinline__ uint32_t f2tf32(float x) {
    uint32_t u;
    asm("cvt.rna.tf32.f32 %0, %1;" : "=r"(u) : "f"(x));
    return u;
}
__device__ __forceinline__ float f2tf32f(float x) {
    return __uint_as_float(f2tf32(x));
}

__device__ __forceinline__ void mma_m16n8k8(float (&d)[4],
    uint32_t a0, uint32_t a1, uint32_t a2, uint32_t a3,
    uint32_t b0, uint32_t b1)
{
    asm volatile(
        "mma.sync.aligned.m16n8k8.row.col.f32.tf32.tf32.f32 "
        "{%0,%1,%2,%3}, {%4,%5,%6,%7}, {%8,%9}, {%0,%1,%2,%3};\n"
        : "+f"(d[0]), "+f"(d[1]), "+f"(d[2]), "+f"(d[3])
        : "r"(a0), "r"(a1), "r"(a2), "r"(a3), "r"(b0), "r"(b1));
}

// ---------------------------------------------------------------------------
// Shared tf32 GEMM core: out[m0:m0+128, n0:n0+128] = A[.,512] @ W[512,512]+bias
// 256 threads = 8 warps (4x2), warp tile 32x64, BK=16, double-buffered smem.
// ---------------------------------------------------------------------------
__device__ __forceinline__ void gemm_core(const float* __restrict__ A,
    const float* __restrict__ W, const float* __restrict__ bias,
    float* __restrict__ out, int Mrows, int m0, int n0)
{
    __shared__ float sA[2][16][136];   // [k][m], stride 136 -> conflict-free frags
    __shared__ float sB[2][16][136];   // [k][n]

    const int tid = threadIdx.x;
    const int lane = tid & 31;
    const int wid = tid >> 5;
    const int wm = (wid >> 1) * 32;
    const int wn = (wid & 1) * 64;
    const int g = lane >> 2;   // groupID
    const int tg = lane & 3;   // thread-in-group

    // staging mappings
    const int ar = tid >> 1;          // A row within tile (0..127)
    const int akq = (tid & 1) * 8;    // A k-offset (0 or 8)
    const int bkr = tid >> 4;         // W k-row (0..15)
    const int bn = (tid & 15) * 8;    // W n-offset

    float acc[2][8][4];
#pragma unroll
    for (int im = 0; im < 2; ++im)
#pragma unroll
        for (int in = 0; in < 8; ++in)
#pragma unroll
            for (int j = 0; j < 4; ++j) acc[im][in][j] = 0.f;

    const bool arow_ok = (m0 + ar) < Mrows;
    const float* aptr = A + (size_t)(m0 + ar) * 512 + akq;
    const float* wptr = W + (size_t)bkr * 512 + n0 + bn;

    float4 ra0, ra1, rb0, rb1;

    auto load_stage = [&](int k0) {
        if (arow_ok) {
            ra0 = *reinterpret_cast<const float4*>(aptr + k0);
            ra1 = *reinterpret_cast<const float4*>(aptr + k0 + 4);
        } else {
            ra0 = make_float4(0.f, 0.f, 0.f, 0.f);
            ra1 = ra0;
        }
        rb0 = *reinterpret_cast<const float4*>(wptr + (size_t)k0 * 512);
        rb1 = *reinterpret_cast<const float4*>(wptr + (size_t)k0 * 512 + 4);
    };
    auto store_stage = [&](int buf) {
        sA[buf][akq + 0][ar] = f2tf32f(ra0.x);
        sA[buf][akq + 1][ar] = f2tf32f(ra0.y);
        sA[buf][akq + 2][ar] = f2tf32f(ra0.z);
        sA[buf][akq + 3][ar] = f2tf32f(ra0.w);
        sA[buf][akq + 4][ar] = f2tf32f(ra1.x);
        sA[buf][akq + 5][ar] = f2tf32f(ra1.y);
        sA[buf][akq + 6][ar] = f2tf32f(ra1.z);
        sA[buf][akq + 7][ar] = f2tf32f(ra1.w);
        float4 c0 = make_float4(f2tf32f(rb0.x), f2tf32f(rb0.y), f2tf32f(rb0.z), f2tf32f(rb0.w));
        float4 c1 = make_float4(f2tf32f(rb1.x), f2tf32f(rb1.y), f2tf32f(rb1.z), f2tf32f(rb1.w));
        *reinterpret_cast<float4*>(&sB[buf][bkr][bn]) = c0;
        *reinterpret_cast<float4*>(&sB[buf][bkr][bn + 4]) = c1;
    };

    load_stage(0);
    store_stage(0);
    __syncthreads();

#pragma unroll 1
    for (int it = 0; it < 32; ++it) {
        const int buf = it & 1;
        if (it < 31) load_stage((it + 1) * 16);

#pragma unroll
        for (int kk = 0; kk < 16; kk += 8) {
            uint32_t af[2][4];
#pragma unroll
            for (int im = 0; im < 2; ++im) {
                af[im][0] = __float_as_uint(sA[buf][kk + tg    ][wm + im * 16 + g    ]);
                af[im][1] = __float_as_uint(sA[buf][kk + tg    ][wm + im * 16 + g + 8]);
                af[im][2] = __float_as_uint(sA[buf][kk + tg + 4][wm + im * 16 + g    ]);
                af[im][3] = __float_as_uint(sA[buf][kk + tg + 4][wm + im * 16 + g + 8]);
            }
#pragma unroll
            for (int in = 0; in < 8; ++in) {
                const uint32_t b0 = __float_as_uint(sB[buf][kk + tg    ][wn + in * 8 + g]);
                const uint32_t b1 = __float_as_uint(sB[buf][kk + tg + 4][wn + in * 8 + g]);
#pragma unroll
                for (int im = 0; im < 2; ++im)
                    mma_m16n8k8(acc[im][in], af[im][0], af[im][1], af[im][2], af[im][3], b0, b1);
            }
        }

        if (it < 31) {
            store_stage(1 - buf);
            __syncthreads();
        }
    }

    // epilogue: bias + store
#pragma unroll
    for (int in = 0; in < 8; ++in) {
        const int col = n0 + wn + in * 8 + tg * 2;
        const float2 bb = *reinterpret_cast<const float2*>(bias + col);
#pragma unroll
        for (int im = 0; im < 2; ++im) {
            const int r0 = m0 + wm + im * 16 + g;
            if (r0 < Mrows) {
                float2 v = make_float2(acc[im][in][0] + bb.x, acc[im][in][1] + bb.y);
                *reinterpret_cast<float2*>(out + (size_t)r0 * 512 + col) = v;
            }
            const int r1 = r0 + 8;
            if (r1 < Mrows) {
                float2 v = make_float2(acc[im][in][2] + bb.x, acc[im][in][3] + bb.y);
                *reinterpret_cast<float2*>(out + (size_t)r1 * 512 + col) = v;
            }
        }
    }
}

// ---------------------------------------------------------------------------
// Fused projections: Q,K,V (3 x 128 blocks) + KC,VC (2 x 8 blocks) = 400 blocks
// ---------------------------------------------------------------------------
__global__ __launch_bounds__(256) void proj_kernel(
    const float* __restrict__ x, const float* __restrict__ c,
    const float* __restrict__ Wq, const float* __restrict__ bq,
    const float* __restrict__ Wk, const float* __restrict__ bk,
    const float* __restrict__ Wv, const float* __restrict__ bv,
    const float* __restrict__ Wkc, const float* __restrict__ bkc,
    const float* __restrict__ Wvc, const float* __restrict__ bvc,
    float* __restrict__ Qb, float* __restrict__ Kb, float* __restrict__ Vb,
    float* __restrict__ KCb, float* __restrict__ VCb)
{
    const int bid = blockIdx.x;
    const float *A, *W, *bias;
    float* out;
    int Mrows, m0, n0;
    if (bid < 384) {
        const int t = bid / 128, l = bid % 128;
        m0 = (l >> 2) * 128;
        n0 = (l & 3) * 128;
        A = x; Mrows = BT;
        W = (t == 0) ? Wq : ((t == 1) ? Wk : Wv);
        bias = (t == 0) ? bq : ((t == 1) ? bk : bv);
        out = (t == 0) ? Qb : ((t == 1) ? Kb : Vb);
    } else {
        const int r = bid - 384;
        const int t = r / 8, l = r % 8;
        m0 = (l >> 2) * 128;
        n0 = (l & 3) * 128;
        A = c; Mrows = MSMALL;
        W = t ? Wvc : Wkc;
        bias = t ? bvc : bkc;
        out = t ? VCb : KCb;
    }
    gemm_core(A, W, bias, out, Mrows, m0, n0);
}

// Fused gate GEMMs: G1 = Y@Wg1+bg1, G2 = YC@Wg2+bg2 (2 x 128 blocks)
__global__ __launch_bounds__(256) void gates_kernel(
    const float* __restrict__ Yb, const float* __restrict__ YCb,
    const float* __restrict__ Wg1, const float* __restrict__ bg1,
    const float* __restrict__ Wg2, const float* __restrict__ bg2,
    float* __restrict__ G1, float* __restrict__ G2)
{
    const int bid = blockIdx.x;
    const int t = bid >> 7;
    const int l = bid & 127;
    const int m0 = (l >> 2) * 128;
    const int n0 = (l & 3) * 128;
    const float* A = t ? YCb : Yb;
    const float* W = t ? Wg2 : Wg1;
    const float* bias = t ? bg2 : bg1;
    float* out = t ? G2 : G1;
    gemm_core(A, W, bias, out, BT, m0, n0);
}

// Final projection: out = F @ Wp + bp (128 blocks)
__global__ __launch_bounds__(256) void final_gemm_kernel(
    const float* __restrict__ F, const float* __restrict__ Wp,
    const float* __restrict__ bp, float* __restrict__ out)
{
    const int l = blockIdx.x;
    const int m0 = (l >> 2) * 128;
    const int n0 = (l & 3) * 128;
    gemm_core(F, Wp, bp, out, BT, m0, n0);
}

// ---------------------------------------------------------------------------
// Flash self-attention (causal) with tf32 mma. 64 queries/block, 4 warps
// (warp = 16 query rows), jb loop over 64-key tiles. Q pre-scaled by 1/8.
// grid: (T/64, B*H), 128 threads, dynamic smem 76800B.
// ---------------------------------------------------------------------------
#define SQ_STRIDE 76
#define SV_STRIDE 72

__global__ __launch_bounds__(128) void self_attn_mma(
    const float* __restrict__ Q, const float* __restrict__ K,
    const float* __restrict__ V, float* __restrict__ Y)
{
    extern __shared__ float sm[];
    float* sQ = sm;                         // [64][76]
    float* sK = sQ + 64 * SQ_STRIDE;        // [64][76]
    float* sP = sK + 64 * SQ_STRIDE;        // [64][76]
    float* sV = sP + 64 * SQ_STRIDE;        // [64][72]

    const int qb = blockIdx.x;
    const int bh = blockIdx.y;
    const int b = bh >> 3;
    const int h = bh & 7;
    const int tid = threadIdx.x;
    const int lane = tid & 31;
    const int wid = tid >> 5;
    const int g = lane >> 2;
    const int tg = lane & 3;

    const size_t base = ((size_t)b * TLEN) * CDIM + h * DHEAD;

    // load + scale + tf32-convert Q tile
    for (int i = tid; i < 64 * 64; i += 128) {
        const int r = i >> 6, cc = i & 63;
        sQ[r * SQ_STRIDE + cc] =
            f2tf32f(Q[base + (size_t)(qb * 64 + r) * CDIM + cc] * 0.125f);
    }

    float o[8][4];
#pragma unroll
    for (int in = 0; in < 8; ++in)
#pragma unroll
        for (int j = 0; j < 4; ++j) o[in][j] = 0.f;
    float mrow[2] = {-1e30f, -1e30f};
    float lrow[2] = {0.f, 0.f};

    const int rA = wid * 16 + g;       // local query row (c0/c1)
    const int qrA = qb * 64 + rA;      // global query row
    const int qrB = qrA + 8;

    for (int jb = 0; jb <= qb; ++jb) {
        __syncthreads();
        for (int i = tid; i < 64 * 64; i += 128) {
            const int r = i >> 6, cc = i & 63;
            const size_t gidx = base + (size_t)(jb * 64 + r) * CDIM + cc;
            sK[r * SQ_STRIDE + cc] = f2tf32f(K[gidx]);
            sV[r * SV_STRIDE + cc] = f2tf32f(V[gidx]);
        }
        __syncthreads();

        // S = Q @ K^T  (scaled already)
        float s[8][4];
#pragma unroll
        for (int in = 0; in < 8; ++in)
#pragma unroll
            for (int j = 0; j < 4; ++j) s[in][j] = 0.f;

#pragma unroll
        for (int kk = 0; kk < 64; kk += 8) {
            const uint32_t a0 = __float_as_uint(sQ[(rA    ) * SQ_STRIDE + kk + tg    ]);
            const uint32_t a1 = __float_as_uint(sQ[(rA + 8) * SQ_STRIDE + kk + tg    ]);
            const uint32_t a2 = __float_as_uint(sQ[(rA    ) * SQ_STRIDE + kk + tg + 4]);
            const uint32_t a3 = __float_as_uint(sQ[(rA + 8) * SQ_STRIDE + kk + tg + 4]);
#pragma unroll
            for (int in = 0; in < 8; ++in) {
                const uint32_t b0 = __float_as_uint(sK[(in * 8 + g) * SQ_STRIDE + kk + tg    ]);
                const uint32_t b1 = __float_as_uint(sK[(in * 8 + g) * SQ_STRIDE + kk + tg + 4]);
                mma_m16n8k8(s[in], a0, a1, a2, a3, b0, b1);
            }
        }

        // causal mask (diagonal block only)
        if (jb == qb) {
#pragma unroll
            for (int in = 0; in < 8; ++in) {
                const int cj = jb * 64 + in * 8 + tg * 2;
                if (cj     > qrA) s[in][0] = -1e30f;
                if (cj + 1 > qrA) s[in][1] = -1e30f;
                if (cj     > qrB) s[in][2] = -1e30f;
                if (cj + 1 > qrB) s[in][3] = -1e30f;
            }
        }

        // online softmax over the two rows this thread owns
        float rmA = -1e30f, rmB = -1e30f;
#pragma unroll
        for (int in = 0; in < 8; ++in) {
            rmA = fmaxf(rmA, fmaxf(s[in][0], s[in][1]));
            rmB = fmaxf(rmB, fmaxf(s[in][2], s[in][3]));
        }
        rmA = fmaxf(rmA, __shfl_xor_sync(0xffffffffu, rmA, 1));
        rmA = fmaxf(rmA, __shfl_xor_sync(0xffffffffu, rmA, 2));
        rmB = fmaxf(rmB, __shfl_xor_sync(0xffffffffu, rmB, 1));
        rmB = fmaxf(rmB, __shfl_xor_sync(0xffffffffu, rmB, 2));

        const float mA = fmaxf(mrow[0], rmA);
        const float mB = fmaxf(mrow[1], rmB);
        const float cA = __expf(mrow[0] - mA);
        const float cB = __expf(mrow[1] - mB);

        float rsA = 0.f, rsB = 0.f;
#pragma unroll
        for (int in = 0; in < 8; ++in) {
            const float p0 = __expf(s[in][0] - mA);
            const float p1 = __expf(s[in][1] - mA);
            const float p2 = __expf(s[in][2] - mB);
            const float p3 = __expf(s[in][3] - mB);
            rsA += p0 + p1;
            rsB += p2 + p3;
            const int col = in * 8 + tg * 2;
            *reinterpret_cast<float2*>(&sP[(rA    ) * SQ_STRIDE + col]) =
                make_float2(f2tf32f(p0), f2tf32f(p1));
            *reinterpret_cast<float2*>(&sP[(rA + 8) * SQ_STRIDE + col]) =
                make_float2(f2tf32f(p2), f2tf32f(p3));
        }
        rsA += __shfl_xor_sync(0xffffffffu, rsA, 1);
        rsA += __shfl_xor_sync(0xffffffffu, rsA, 2);
        rsB += __shfl_xor_sync(0xffffffffu, rsB, 1);
        rsB += __shfl_xor_sync(0xffffffffu, rsB, 2);

        lrow[0] = lrow[0] * cA + rsA;
        lrow[1] = lrow[1] * cB + rsB;
        mrow[0] = mA;
        mrow[1] = mB;

#pragma unroll
        for (int in = 0; in < 8; ++in) {
            o[in][0] *= cA;
            o[in][1] *= cA;
            o[in][2] *= cB;
            o[in][3] *= cB;
        }
        __syncwarp();

        // O += P @ V
#pragma unroll
        for (int kk = 0; kk < 64; kk += 8) {
            const uint32_t a0 = __float_as_uint(sP[(rA    ) * SQ_STRIDE + kk + tg    ]);
            const uint32_t a1 = __float_as_uint(sP[(rA + 8) * SQ_STRIDE + kk + tg    ]);
            const uint32_t a2 = __float_as_uint(sP[(rA    ) * SQ_STRIDE + kk + tg + 4]);
            const uint32_t a3 = __float_as_uint(sP[(rA + 8) * SQ_STRIDE + kk + tg + 4]);
#pragma unroll
            for (int in = 0; in < 8; ++in) {
                const uint32_t b0 = __float_as_uint(sV[(kk + tg    ) * SV_STRIDE + in * 8 + g]);
                const uint32_t b1 = __float_as_uint(sV[(kk + tg + 4) * SV_STRIDE + in * 8 + g]);
                mma_m16n8k8(o[in], a0, a1, a2, a3, b0, b1);
            }
        }
    }

    const float invA = 1.f / lrow[0];
    const float invB = 1.f / lrow[1];
#pragma unroll
    for (int in = 0; in < 8; ++in) {
        const int col = in * 8 + tg * 2;
        *reinterpret_cast<float2*>(Y + base + (size_t)qrA * CDIM + col) =
            make_float2(o[in][0] * invA, o[in][1] * invA);
        *reinterpret_cast<float2*>(Y + base + (size_t)qrB * CDIM + col) =
            make_float2(o[in][2] * invB, o[in][3] * invB);
    }
}

// ---------------------------------------------------------------------------
// Cross-attention: 77 keys per head, padding mask. One thread per query row.
// grid: (T/128, B*H), 128 threads.
// ---------------------------------------------------------------------------
__global__ __launch_bounds__(128) void cross_attn_kernel(
    const float* __restrict__ Q, const float* __restrict__ Kc,
    const float* __restrict__ Vc, const int* __restrict__ pad,
    float* __restrict__ Yc)
{
    const int bh = blockIdx.y;
    const int b = bh >> 3;
    const int h = bh & 7;
    const int row0 = blockIdx.x * 128;
    const int tid = threadIdx.x;

    __shared__ float sQ[128 * 65];

    const size_t qbase = ((size_t)b * TLEN) * CDIM + h * DHEAD;
    for (int i = tid; i < 128 * 64; i += 128) {
        const int r = i >> 6, c = i & 63;
        sQ[r * 65 + c] = Q[qbase + (size_t)(row0 + r) * CDIM + c];
    }
    __syncthreads();

    const float* kb = Kc + ((size_t)b * MLEN) * CDIM + h * DHEAD;
    const float* vb = Vc + ((size_t)b * MLEN) * CDIM + h * DHEAD;
    const int* pb = pad + b * MLEN;
    const float* qrow = &sQ[tid * 65];

    float m = -1e30f;
    for (int j = 0; j < MLEN; ++j) {
        if (pb[j] == 0) continue;
        float dot = 0.f;
        const float* kr = kb + (size_t)j * CDIM;
#pragma unroll 16
        for (int d = 0; d < 64; ++d) dot = fmaf(qrow[d], kr[d], dot);
        m = fmaxf(m, dot * 0.125f);
    }

    float l = 0.f;
    float o[64];
#pragma unroll
    for (int d = 0; d < 64; ++d) o[d] = 0.f;

    for (int j = 0; j < MLEN; ++j) {
        if (pb[j] == 0) continue;
        float dot = 0.f;
        const float* kr = kb + (size_t)j * CDIM;
#pragma unroll 16
        for (int d = 0; d < 64; ++d) dot = fmaf(qrow[d], kr[d], dot);
        const float p = __expf(dot * 0.125f - m);
        l += p;
        const float* vr = vb + (size_t)j * CDIM;
#pragma unroll 16
        for (int d = 0; d < 64; ++d) o[d] = fmaf(p, vr[d], o[d]);
    }

    const float inv = (l > 0.f) ? (1.f / l) : 0.f;
    float* yout = Yc + qbase + (size_t)(row0 + tid) * CDIM;
#pragma unroll 16
    for (int d = 0; d < 64; ++d) yout[d] = o[d] * inv;
}

// ---------------------------------------------------------------------------
// fused = sigmoid(g1) * yc + sigmoid(g2) * y
// ---------------------------------------------------------------------------
__device__ __forceinline__ float sigf(float x) {
    return 1.f / (1.f + __expf(-x));
}

__global__ __launch_bounds__(256) void gate_fuse_kernel(
    const float* __restrict__ g1, const float* __restrict__ g2,
    const float* __restrict__ y, const float* __restrict__ yc,
    float* __restrict__ out)
{
    const int i = blockIdx.x * blockDim.x + threadIdx.x;  // float4 index
    const float4 a = reinterpret_cast<const float4*>(g1)[i];
    const float4 bg = reinterpret_cast<const float4*>(g2)[i];
    const float4 yv = reinterpret_cast<const float4*>(y)[i];
    const float4 yw = reinterpret_cast<const float4*>(yc)[i];
    float4 o;
    o.x = sigf(a.x) * yw.x + sigf(bg.x) * yv.x;
    o.y = sigf(a.y) * yw.y + sigf(bg.y) * yv.y;
    o.z = sigf(a.z) * yw.z + sigf(bg.z) * yv.z;
    o.w = sigf(a.w) * yw.w + sigf(bg.w) * yv.w;
    reinterpret_cast<float4*>(out)[i] = o;
}

// ---------------------------------------------------------------------------
// Launch
// ---------------------------------------------------------------------------
extern "C" void kernel_launch(void* const* d_in, const int* in_sizes, int n_in,
                              void* d_out, int out_size)
{
    const float* x  = (const float*)d_in[0];
    const float* c  = (const float*)d_in[1];
    // d_in[2] attn_mask: fixed causal tril -> handled analytically
    const int* pad  = (const int*)d_in[3];
    const float* Wq = (const float*)d_in[4];
    const float* bq = (const float*)d_in[5];
    const float* Wk = (const float*)d_in[6];
    const float* bk = (const float*)d_in[7];
    const float* Wv = (const float*)d_in[8];
    const float* bv = (const float*)d_in[9];
    const float* Wkc = (const float*)d_in[10];
    const float* bkc = (const float*)d_in[11];
    const float* Wvc = (const float*)d_in[12];
    const float* bvc = (const float*)d_in[13];
    const float* Wg1 = (const float*)d_in[14];
    const float* bg1 = (const float*)d_in[15];
    const float* Wg2 = (const float*)d_in[16];
    const float* bg2 = (const float*)d_in[17];
    const float* Wp = (const float*)d_in[18];
    const float* bp = (const float*)d_in[19];
    float* out = (float*)d_out;

    float* S = nullptr;
    cudaGetSymbolAddress((void**)&S, g_scratch);
    float* Qb  = S + 0ULL * NBIG;
    float* Kb  = S + 1ULL * NBIG;
    float* Vb  = S + 2ULL * NBIG;
    float* Yb  = S + 3ULL * NBIG;
    float* YCb = S + 4ULL * NBIG;
    float* G1b = S + 5ULL * NBIG;
    float* G2b = S + 6ULL * NBIG;
    float* Fb  = S + 7ULL * NBIG;
    float* KCb = S + 8ULL * NBIG;
    float* VCb = S + 8ULL * NBIG + NSMALL;

    const int SMEM_SA = (3 * 64 * SQ_STRIDE + 64 * SV_STRIDE) * (int)sizeof(float); // 76800
    cudaFuncSetAttribute(self_attn_mma,
                         cudaFuncAttributeMaxDynamicSharedMemorySize, SMEM_SA);

    // 1) all five input projections in one launch (400 blocks)
    proj_kernel<<<400, 256>>>(x, c, Wq, bq, Wk, bk, Wv, bv,
                              Wkc, bkc, Wvc, bvc, Qb, Kb, Vb, KCb, VCb);

    // 2) attention branches
    self_attn_mma<<<dim3(TLEN / 64, BATCH * HEADS), 128, SMEM_SA>>>(Qb, Kb, Vb, Yb);
    cross_attn_kernel<<<dim3(TLEN / 128, BATCH * HEADS), 128>>>(Qb, KCb, VCb, pad, YCb);

    // 3) both gate GEMMs in one launch (256 blocks)
    gates_kernel<<<256, 256>>>(Yb, YCb, Wg1, bg1, Wg2, bg2, G1b, G2b);

    // 4) fused = sig(G1)*YC + sig(G2)*Y
    gate_fuse_kernel<<<NBIG / 4 / 256, 256>>>(G1b, G2b, Yb, YCb, Fb);

    // 5) output projection
    final_gemm_kernel<<<128, 256>>>(Fb, Wp, bp, out);
}